// round 17
// baseline (speedup 1.0000x reference)
#include <cuda_runtime.h>
#include <cuda_fp16.h>

// DynamicRouting: B=128, IN=2048, OUT=32, POSE=4, 3 routing iterations.
// poses_out [B,32,4] followed by activations_out [B,32] in d_out.
//
// Pass 0 (lane=o): fp32 votes streamed from DRAM (evict_first), fp16 copy
// written to a 64 MB __device__ scratch (evict_last -> L2-resident) in
// natural [i][o][p] layout.
// Hot passes 1-2 (TRANSPOSED): 8 lanes per input capsule i, 4 output
// capsules per lane. Softmax over o = thread-local sum of 4 exps + 3-step
// shfl.bfly within the 8-lane group -- NO REDUX, no fixed point, pure fp32.
// Per-thread s-partials (16 regs) reduced once per pass via bfly(8,16)+smem.

#define NB 128
#define NI 2048
#define NO 32
#define NP 4
#define EPSF 1e-7f
#define NWARPS 32
#define NTHREADS (NWARPS * 32)
#define NQUAD 16            // pass-0 quads per thread
#define NROUND 16           // hot-pass rounds per thread (4 votes each)

typedef unsigned long long u64;
typedef unsigned int u32;

// 64 MB fp16 vote cache, natural [i][o][p] layout per batch.
__device__ __align__(32) __half vcache[(size_t)NB * NI * NO * NP];

__device__ __forceinline__ u32 h2_to_u32(__half2 h) {
    union { __half2 h; u32 u; } cvt; cvt.h = h; return cvt.u;
}
__device__ __forceinline__ __half2 u32_to_h2(u32 u) {
    union { u32 u; __half2 h; } cvt; cvt.u = u; return cvt.h;
}
__device__ __forceinline__ float ex2_fast(float x) {
    float r;
    asm("ex2.approx.ftz.f32 %0, %1;" : "=f"(r) : "f"(x));
    return r;
}
__device__ __forceinline__ float rcp_fast(float x) {
    float r;
    asm("rcp.approx.ftz.f32 %0, %1;" : "=f"(r) : "f"(x));
    return r;
}

// fp32 vote load: read-only, streaming (evict_first).
__device__ __forceinline__ float4 ldg_stream(const float4* p, u64 pol) {
    float4 v;
    asm("ld.global.nc.L2::cache_hint.v4.f32 {%0,%1,%2,%3}, [%4], %5;"
        : "=f"(v.x), "=f"(v.y), "=f"(v.z), "=f"(v.w)
        : "l"(p), "l"(pol));
    return v;
}
// 8-byte scratch store (one fp16 vote) with evict_last policy.
__device__ __forceinline__ void st_cache2(__half* p, u32 a, u32 b, u64 pol) {
    asm volatile("st.global.L2::cache_hint.v2.b32 [%0], {%1,%2}, %3;"
                 :: "l"(p), "r"(a), "r"(b), "l"(pol) : "memory");
}
// 16-byte coherent scratch load with evict_last policy.
__device__ __forceinline__ void ld_coh4(const __half* p, u32* r, u64 pol) {
    asm("ld.global.L2::cache_hint.v4.b32 {%0,%1,%2,%3}, [%4], %5;"
        : "=r"(r[0]), "=r"(r[1]), "=r"(r[2]), "=r"(r[3])
        : "l"(p), "l"(pol));
}

__global__ __launch_bounds__(NTHREADS, 1)
void routing_kernel(const float4* __restrict__ votes, float* __restrict__ out) {
    const int b    = blockIdx.x;
    const int tid  = threadIdx.x;
    const int w    = tid >> 5;
    const int lane = tid & 31;

    __shared__ float4 part4[NWARPS][NO];   // [warp][o] -> s partial (p in .xyzw)
    __shared__ float4 vsh4[2][NO];         // v1, v2
    __shared__ float  s_sh[NO * NP];       // reduced s

    u64 pol_first, pol_last;
    asm("createpolicy.fractional.L2::evict_first.b64 %0, 1.0;" : "=l"(pol_first));
    asm("createpolicy.fractional.L2::evict_last.b64 %0, 1.0;"  : "=l"(pol_last));

    const float4* vb = votes + (size_t)b * (NI * NO);
    __half*       cb = vcache + (size_t)b * (NI * NO * NP);

    // Hot-pass geometry: 8 lanes per i, 4 o's per lane.
    const int isub  = lane >> 3;        // 0..3: i-subgroup within warp
    const int obase = (lane & 7) * 4;   // this lane's first o

#pragma unroll
    for (int it = 0; it < 3; ++it) {
        if (it == 0) {
            // ---- pass 0: lane = o, stream fp32, write fp16 scratch ----
            float ax = 0.f, ay = 0.f, az = 0.f, aw = 0.f;
#pragma unroll 2
            for (int q = 0; q < NQUAD; ++q) {
#pragma unroll
                for (int h = 0; h < 4; ++h) {
                    const int i = w + 32 * (4 * q + h);
                    float4 vt = ldg_stream(&vb[i * NO + lane], pol_first);
                    u32 lo = h2_to_u32(__floats2half2_rn(vt.x, vt.y));
                    u32 hi = h2_to_u32(__floats2half2_rn(vt.z, vt.w));
                    st_cache2(cb + ((size_t)i * NO + lane) * NP, lo, hi, pol_last);
                    ax += vt.x; ay += vt.y; az += vt.z; aw += vt.w;
                }
            }
            part4[w][lane] = make_float4(ax * (1.0f / 32.0f), ay * (1.0f / 32.0f),
                                         az * (1.0f / 32.0f), aw * (1.0f / 32.0f));
        } else {
            // ---- hot pass: transposed layout, shfl softmax ----
            const float l2e = 1.44269504f;
            float4 wv[4];                // pre-scaled v[obase+ol]*log2e
#pragma unroll
            for (int ol = 0; ol < 4; ++ol) {
                float4 a = vsh4[0][obase + ol];
                if (it == 2) {
                    float4 c = vsh4[1][obase + ol];
                    a.x += c.x; a.y += c.y; a.z += c.z; a.w += c.w;
                }
                wv[ol] = make_float4(a.x * l2e, a.y * l2e, a.z * l2e, a.w * l2e);
            }
            float acc[16];
#pragma unroll
            for (int k = 0; k < 16; ++k) acc[k] = 0.f;

            // Thread's stream: i = w*64 + r*4 + isub, o = obase..obase+3.
            const __half* tp = cb + ((size_t)(w * 64 + isub) * NO + obase) * NP;
#pragma unroll 4
            for (int r = 0; r < NROUND; ++r) {
                const __half* ra = tp + (size_t)r * (4 * NO * NP);
                u32 pk[8];
                ld_coh4(ra,     pk,     pol_last);
                ld_coh4(ra + 8, pk + 4, pol_last);
                float ef[4];
                float sum = 0.f;
#pragma unroll
                for (int ol = 0; ol < 4; ++ol) {
                    float2 f01 = __half22float2(u32_to_h2(pk[2 * ol + 0]));
                    float2 f23 = __half22float2(u32_to_h2(pk[2 * ol + 1]));
                    float t = f01.x * wv[ol].x;
                    t = fmaf(f01.y, wv[ol].y, t);
                    t = fmaf(f23.x, wv[ol].z, t);
                    t = fmaf(f23.y, wv[ol].w, t);
                    ef[ol] = ex2_fast(t);
                    sum += ef[ol];
                }
                // softmax denominator across the 8 lanes of this i
                sum += __shfl_xor_sync(0xffffffffu, sum, 1);
                sum += __shfl_xor_sync(0xffffffffu, sum, 2);
                sum += __shfl_xor_sync(0xffffffffu, sum, 4);
                float inv = rcp_fast(sum);
#pragma unroll
                for (int ol = 0; ol < 4; ++ol) {
                    float c = ef[ol] * inv;
                    float2 f01 = __half22float2(u32_to_h2(pk[2 * ol + 0]));
                    float2 f23 = __half22float2(u32_to_h2(pk[2 * ol + 1]));
                    acc[ol * 4 + 0] = fmaf(c, f01.x, acc[ol * 4 + 0]);
                    acc[ol * 4 + 1] = fmaf(c, f01.y, acc[ol * 4 + 1]);
                    acc[ol * 4 + 2] = fmaf(c, f23.x, acc[ol * 4 + 2]);
                    acc[ol * 4 + 3] = fmaf(c, f23.y, acc[ol * 4 + 3]);
                }
            }
            // Reduce the 4 i-subgroups within the warp (same o-subset).
#pragma unroll
            for (int k = 0; k < 16; ++k)
                acc[k] += __shfl_xor_sync(0xffffffffu, acc[k], 8);
#pragma unroll
            for (int k = 0; k < 16; ++k)
                acc[k] += __shfl_xor_sync(0xffffffffu, acc[k], 16);
            if (lane < 8) {
#pragma unroll
                for (int ol = 0; ol < 4; ++ol)
                    part4[w][lane * 4 + ol] =
                        make_float4(acc[ol * 4 + 0], acc[ol * 4 + 1],
                                    acc[ol * 4 + 2], acc[ol * 4 + 3]);
            }
        }
        __syncthreads();

        // Reduce the 32 warp-partials: 128 threads, one per (o,p)
        if (tid < NO * NP) {
            const float* pf = (const float*)part4;
            float s = 0.f;
#pragma unroll
            for (int ww = 0; ww < NWARPS; ++ww)
                s += pf[ww * (NO * NP) + tid];
            s_sh[tid] = s;
        }
        __syncthreads();

        // Squash per output capsule (32 threads)
        if (tid < NO) {
            float sx = s_sh[tid * 4 + 0];
            float sy = s_sh[tid * 4 + 1];
            float sz = s_sh[tid * 4 + 2];
            float sw = s_sh[tid * 4 + 3];
            float n2 = sx * sx + sy * sy + sz * sz + sw * sw + EPSF;
            // v = (n2/(1+n2)) * s/sqrt(n2)  ==  s * sqrt(n2)/(1+n2)
            float f  = sqrtf(n2) / (1.0f + n2);
            float vx = sx * f, vy = sy * f, vz = sz * f, vw = sw * f;
            if (it < 2) {
                vsh4[it][tid] = make_float4(vx, vy, vz, vw);
            } else {
                float* po = out + ((size_t)b * NO + tid) * NP;
                po[0] = vx; po[1] = vy; po[2] = vz; po[3] = vw;
                float a2 = vx * vx + vy * vy + vz * vz + vw * vw + EPSF;
                out[(size_t)NB * NO * NP + (size_t)b * NO + tid] = sqrtf(a2);
            }
        }
        __syncthreads();
    }
}

extern "C" void kernel_launch(void* const* d_in, const int* in_sizes, int n_in,
                              void* d_out, int out_size) {
    const float4* votes = (const float4*)d_in[0];   // [B, I, O, P] fp32, 16B-aligned
    // d_in[1] = activations_in — unused by the reference computation
    float* out = (float*)d_out;
    routing_kernel<<<NB, NTHREADS>>>(votes, out);
}